// round 10
// baseline (speedup 1.0000x reference)
#include <cuda_runtime.h>

#define VOCAB 10000
#define EMB   16
#define HID   32
#define NCLS  2
#define BATCH 4096
#define SEQ   512

typedef unsigned long long ull;

#define TANH_C 2.885390081777927f   // 2*log2(e): tanh(x) = 1 - 2/(exp2(x*C)+1)

// Prescaled projected embedding: g_projC[t][h] = C * (sum_e emb[t][e]*W_ih[h][e] + b_ih[h] + b_hh[h])
__device__ float g_projC[VOCAB * HID];

__global__ void build_proj_kernel(const float* __restrict__ emb,
                                  const float* __restrict__ W_ih,
                                  const float* __restrict__ b_ih,
                                  const float* __restrict__ b_hh) {
    int t    = blockIdx.x * (blockDim.x >> 5) + (threadIdx.x >> 5);
    int lane = threadIdx.x & 31;
    if (t >= VOCAB) return;
    float acc = __ldg(b_ih + lane) + __ldg(b_hh + lane);
#pragma unroll
    for (int e = 0; e < EMB; e++) {
        acc = fmaf(__ldg(emb + t * EMB + e), __ldg(W_ih + lane * EMB + e), acc);
    }
    g_projC[t * HID + lane] = acc * TANH_C;
}

__device__ __forceinline__ ull pack2(float lo, float hi) {
    ull u;
    asm("mov.b64 %0, {%1, %2};" : "=l"(u) : "f"(lo), "f"(hi));
    return u;
}
__device__ __forceinline__ ull fma2(ull a, ull b, ull c) {
    asm("fma.rn.f32x2 %0, %1, %2, %3;" : "=l"(c) : "l"(a), "l"(b), "l"(c));
    return c;
}
__device__ __forceinline__ ull add2(ull a, ull b) {
    ull c;
    asm("add.rn.f32x2 %0, %1, %2;" : "=l"(c) : "l"(a), "l"(b));
    return c;
}
// 64-bit butterfly shuffle: two b32 shfls on the register-pair halves.
__device__ __forceinline__ ull shfl64_xor(ull v, int m) {
    unsigned lo, hi;
    asm("mov.b64 {%0, %1}, %2;" : "=r"(lo), "=r"(hi) : "l"(v));
    lo = __shfl_xor_sync(0xffffffffu, lo, m);
    hi = __shfl_xor_sync(0xffffffffu, hi, m);
    ull r;
    asm("mov.b64 %0, {%1, %2};" : "=l"(r) : "r"(lo), "r"(hi));
    return r;
}
// 128-bit shared load -> two packed f32x2 operands (volatile: addresses repeat).
__device__ __forceinline__ void lds2(ull& a, ull& b, unsigned addr) {
    asm volatile("ld.shared.v2.u64 {%0, %1}, [%2];" : "=l"(a), "=l"(b) : "r"(addr));
}

// Split-K layout: lane = (q = lane>>2, c = lane&3).
//  - owns h-chunk k in [8c, 8c+8)  (2 LDS.128/step)
//  - accumulator i = packed (even/odd k) partial for output row  q + 8*(c^i)
//  - fully-PACKED xor-butterfly (6 shfl + 3 add2), single unpack+fadd at the end;
//    output p = q+8c lands on this lane.
__global__ void __launch_bounds__(64, 14) rnn_step_kernel(
    const int* __restrict__ x,
    const float* __restrict__ W_hh,
    const float* __restrict__ W_fc,
    const float* __restrict__ b_fc,
    float* __restrict__ out) {

    int wl   = threadIdx.x >> 5;
    int lane = threadIdx.x & 31;
    int q    = lane >> 2;
    int c    = lane & 3;
    int p    = q + 8 * c;            // the output index this lane finalizes
    int b    = blockIdx.x * 2 + wl;

    __shared__ __align__(16) float hbuf[2][2][HID];

    // w2[i*4 + t] pairs with accumulator i: W_hh[q + 8*(c^i)][8c + 2t .. +2).
    ull w2[16];
#pragma unroll
    for (int i = 0; i < 4; i++) {
        const float2* wr = (const float2*)(W_hh + (q + 8 * (c ^ i)) * HID + 8 * c);
#pragma unroll
        for (int t = 0; t < 4; t++) {
            float2 wf = __ldg(wr + t);
            w2[i * 4 + t] = pack2(wf.x, wf.y);
        }
    }

    unsigned hb0 = (unsigned)__cvta_generic_to_shared(&hbuf[wl][0][0]) + c * 32;
    unsigned hb1 = (unsigned)__cvta_generic_to_shared(&hbuf[wl][1][0]) + c * 32;

    const int4* xb4 = (const int4*)(x + b * SEQ);

    hbuf[wl][0][p] = 0.0f;
    float h = 0.0f;

    // Prime the 2-deep proj prefetch pipeline (tokens 0,1).
    int4 tc = __ldg(xb4);
    float xpA = __ldg(&g_projC[tc.x * HID + p]);
    float xpB = __ldg(&g_projC[tc.y * HID + p]);

#define STEP(PAR, XP, TOKPF)                                                   \
    {                                                                          \
        float xuC = (XP);                                                      \
        (XP) = __ldg(&g_projC[(TOKPF) * HID + p]); /* prefetch s+2 */          \
        __syncwarp();                                                          \
        unsigned src = (PAR) ? hb1 : hb0;                                      \
        ull hp0, hp1, hp2, hp3;                                                \
        lds2(hp0, hp1, src);                                                   \
        lds2(hp2, hp3, src + 16);                                              \
        ull a0 = 0, a1 = 0, a2 = 0, a3 = 0;                                    \
        a0 = fma2(hp0, w2[0],  a0); a1 = fma2(hp0, w2[4],  a1);                \
        a2 = fma2(hp0, w2[8],  a2); a3 = fma2(hp0, w2[12], a3);                \
        a0 = fma2(hp1, w2[1],  a0); a1 = fma2(hp1, w2[5],  a1);                \
        a2 = fma2(hp1, w2[9],  a2); a3 = fma2(hp1, w2[13], a3);                \
        a0 = fma2(hp2, w2[2],  a0); a1 = fma2(hp2, w2[6],  a1);                \
        a2 = fma2(hp2, w2[10], a2); a3 = fma2(hp2, w2[14], a3);                \
        a0 = fma2(hp3, w2[3],  a0); a1 = fma2(hp3, w2[7],  a1);                \
        a2 = fma2(hp3, w2[11], a2); a3 = fma2(hp3, w2[15], a3);                \
        /* fully-packed permuted butterfly */                                  \
        ull b0 = add2(a0, shfl64_xor(a1, 1));                                  \
        ull b1 = add2(a2, shfl64_xor(a3, 1));                                  \
        ull c0 = add2(b0, shfl64_xor(b1, 2));                                  \
        float lo, hi;                                                          \
        asm("mov.b64 {%0, %1}, %2;" : "=f"(lo), "=f"(hi) : "l"(c0));           \
        float v = lo + hi;                                                     \
        float e;                                                               \
        asm("ex2.approx.f32 %0, %1;" : "=f"(e) : "f"(fmaf(v, TANH_C, xuC)));   \
        float r;                                                               \
        asm("rcp.approx.f32 %0, %1;" : "=f"(r) : "f"(e + 1.0f));               \
        h = fmaf(-2.0f, r, 1.0f);                                              \
        hbuf[wl][(PAR) ^ 1][p] = h;                                            \
    }

    for (int g = 0; g < SEQ / 4; g++) {
        int gn = (g + 1 < SEQ / 4) ? g + 1 : g;   // clamp: trailing prefetches discarded
        int4 tn = __ldg(&xb4[gn]);                // one uniform LDG.128 per 4 steps
        STEP(0, xpA, tc.z);   // s = 4g+0, prefetch s+2
        STEP(1, xpB, tc.w);   // s = 4g+1
        STEP(0, xpA, tn.x);   // s = 4g+2
        STEP(1, xpB, tn.y);   // s = 4g+3
        tc = tn;
    }
#undef STEP

    // Classifier head: lane holds h_final[p]; two full-warp reductions.
    float v0 = h * __ldg(W_fc + p);
    float v1 = h * __ldg(W_fc + HID + p);
#pragma unroll
    for (int o = 16; o > 0; o >>= 1) {
        v0 += __shfl_xor_sync(0xffffffffu, v0, o);
        v1 += __shfl_xor_sync(0xffffffffu, v1, o);
    }
    if (lane == 0) {
        out[b * NCLS + 0] = v0 + __ldg(b_fc + 0);
        out[b * NCLS + 1] = v1 + __ldg(b_fc + 1);
    }
}

extern "C" void kernel_launch(void* const* d_in, const int* in_sizes, int n_in,
                              void* d_out, int out_size) {
    const int*   x    = (const int*)d_in[0];
    const float* emb  = (const float*)d_in[1];
    const float* W_ih = (const float*)d_in[2];
    const float* W_hh = (const float*)d_in[3];
    const float* b_ih = (const float*)d_in[4];
    const float* b_hh = (const float*)d_in[5];
    const float* W_fc = (const float*)d_in[6];
    const float* b_fc = (const float*)d_in[7];
    float* out = (float*)d_out;

    build_proj_kernel<<<(VOCAB + 7) / 8, 256>>>(emb, W_ih, b_ih, b_hh);
    rnn_step_kernel<<<BATCH / 2, 64>>>(x, W_hh, W_fc, b_fc, out);
}